// round 14
// baseline (speedup 1.0000x reference)
#include <cuda_runtime.h>
#include <cuda_fp16.h>
#include <math.h>
#include <float.h>

#define BB 4
#define PP 8192
#define CC 64
#define MM 2048
#define KK 32
#define CIN 67
#define H1 128
#define Q1 64
#define NPIX (BB*MM*KK)
#define BN_EPS 1e-5f
#define FULLMASK 0xffffffffu
#define NTILES 2048
#define GRID_P 296

// ---------------- scratch (fp16 intermediates) ----------------
__device__ __half g_featsT[(size_t)BB*PP*CC];
__device__ int    g_idx[(size_t)BB*MM*KK];
__device__ __half g_h0[(size_t)NPIX*H1];
__device__ __half g_f0[(size_t)NPIX*H1];
__device__ float  g_stats1[2*H1];
__device__ float  g_stats2[2*H1];

// ---------------- helpers ----------------
__device__ __forceinline__ void mma16816(float* c, const unsigned* a, const unsigned* b) {
    asm volatile(
        "mma.sync.aligned.m16n8k16.row.col.f32.f16.f16.f32 "
        "{%0,%1,%2,%3}, {%4,%5,%6,%7}, {%8,%9}, {%0,%1,%2,%3};"
        : "+f"(c[0]), "+f"(c[1]), "+f"(c[2]), "+f"(c[3])
        : "r"(a[0]), "r"(a[1]), "r"(a[2]), "r"(a[3]), "r"(b[0]), "r"(b[1]));
}
__device__ __forceinline__ void cp16(unsigned dst, const void* src) {
    asm volatile("cp.async.ca.shared.global [%0], [%1], 16;\n" :: "r"(dst), "l"(src));
}
#define CP_COMMIT() asm volatile("cp.async.commit_group;\n" ::: "memory")
#define CP_WAIT(n)  asm volatile("cp.async.wait_group %0;\n" :: "n"(n) : "memory")

// ---------------- KNN (+ fused feats transpose, centers, stats zeroing) ----------------
__global__ void __launch_bounds__(256) k_knn(const float* __restrict__ xyz,
                                             const float* __restrict__ feats,
                                             float* __restrict__ out,
                                             int* __restrict__ idxout) {
    int tid = threadIdx.x;

    {   // fused pre: transpose feats (B,C,P) -> featsT (B,P,C) fp16, 64 rows/block
        int row0 = blockIdx.x * 64;
        for (int i = tid; i < 64*32; i += 256) {
            int row = row0 + (i & 63);
            int cp  = i >> 6;
            int b = row >> 13;
            int p = row & (PP-1);
            const float* s = feats + (size_t)b*CC*PP + (size_t)(2*cp)*PP + p;
            ((__half2*)(g_featsT + (size_t)row*CC))[cp] = __floats2half2_rn(s[0], s[PP]);
        }
    }
    if (blockIdx.x == 0 && tid < 2*H1) {
        g_stats1[tid] = 0.f;
        g_stats2[tid] = 0.f;
    }

    int c0   = (blockIdx.x * 8 + (tid >> 5)) * 2;
    int lane = tid & 31;
    int b    = c0 >> 11;
    float cx[2], cy[2], cz[2], cc2[2];
#pragma unroll
    for (int jj = 0; jj < 2; jj++) {
        int ci = c0 + jj;
        int m  = ci & (MM-1);
        int pc;
        if (m == MM-1) pc = PP-1;
        else {
            float t = __fdiv_rn((float)m, (float)(MM-1));
            float v = __fmul_rn((float)(PP-1), t);
            pc = (int)v;
            if (pc > PP-1) pc = PP-1;
        }
        const float* s = xyz + ((size_t)(b*PP + pc))*3;
        cx[jj] = s[0]; cy[jj] = s[1]; cz[jj] = s[2];
        cc2[jj] = cx[jj]*cx[jj] + cy[jj]*cy[jj] + cz[jj]*cz[jj];
        if (lane == jj) {
            out[(size_t)ci*3 + 0] = cx[jj];
            out[(size_t)ci*3 + 1] = cy[jj];
            out[(size_t)ci*3 + 2] = cz[jj];
        }
    }
    const float* xb = xyz + (size_t)b*PP*3;

    float ld[2] = {FLT_MAX, FLT_MAX};
    int   li[2] = {0x7fffffff, 0x7fffffff};
    float kth[2] = {FLT_MAX, FLT_MAX};

    for (int base = 0; base < PP; base += 32) {
        int p = base + lane;
        float x = xb[3*p], y = xb[3*p+1], z = xb[3*p+2];
        float x2 = x*x + y*y + z*z;
#pragma unroll
        for (int jj = 0; jj < 2; jj++) {
            float d = (cc2[jj] + x2) - 2.0f*(cx[jj]*x + cy[jj]*y + cz[jj]*z);
            unsigned mask = __ballot_sync(FULLMASK, d < kth[jj]);
            while (mask) {
                int j = __ffs(mask) - 1; mask &= mask - 1;
                float dj = __shfl_sync(FULLMASK, d, j);
                if (dj < kth[jj]) {
                    int pj = base + j;
                    unsigned lt = __ballot_sync(FULLMASK,
                        (ld[jj] < dj) || (ld[jj] == dj && li[jj] < pj));
                    int pos = __popc(lt);
                    float pd = __shfl_up_sync(FULLMASK, ld[jj], 1);
                    int   pi = __shfl_up_sync(FULLMASK, li[jj], 1);
                    if (lane == pos)      { ld[jj] = dj; li[jj] = pj; }
                    else if (lane > pos)  { ld[jj] = pd; li[jj] = pi; }
                    kth[jj] = __shfl_sync(FULLMASK, ld[jj], 31);
                }
            }
        }
    }
#pragma unroll
    for (int jj = 0; jj < 2; jj++)
        idxout[(size_t)(c0 + jj)*KK + lane] = li[jj];
}

// ================= GEMM1: persistent tiles, cp.async double-buffered gather + MMA =================
__global__ void __launch_bounds__(256, 2) k_gemm1(const float* __restrict__ xyz,
                                                  const float* __restrict__ centers,
                                                  const float* __restrict__ W1,
                                                  const float* __restrict__ b1) {
    extern __shared__ __half sh[];
    __half* Ab = sh;                       // 2 * 128*88
    __half* Bs = sh + 2*128*88;
    unsigned* Bw = (unsigned*)Bs;

    int tid = threadIdx.x, wid = tid >> 5, lane = tid & 31;
    int g = lane >> 2, t = lane & 3;
    int warp_pix = (wid >> 2) * 64, warp_n = (wid & 3) * 32;
    int r = tid >> 1, h = tid & 1;

    for (int i = tid; i < 128*44; i += 256) Bw[i] = 0u;
    {
        __half z = __float2half_rn(0.f);
#pragma unroll
        for (int bufi = 0; bufi < 2; bufi++)
            if (h == 1)
                for (int q = 64; q < 88; q++) Ab[bufi*128*88 + r*88 + q] = z;
    }
    __syncthreads();
    for (int i = tid; i < H1*CIN; i += 256) {
        int o = i / CIN, c = i - o*CIN;
        int col = (c < 3) ? (64 + c) : (c - 3);
        Bs[o*88 + col] = __float2half_rn(W1[i]);
    }
    float bias0[4], bias1[4];
#pragma unroll
    for (int ni = 0; ni < 4; ni++) {
        bias0[ni] = b1[warp_n + ni*8 + 2*t];
        bias1[ni] = b1[warp_n + ni*8 + 2*t + 1];
    }
    unsigned abase = (unsigned)__cvta_generic_to_shared(Ab);

    float ss[4][2], sq[4][2];
#pragma unroll
    for (int ni = 0; ni < 4; ni++) { ss[ni][0]=ss[ni][1]=0.f; sq[ni][0]=sq[ni][1]=0.f; }

    auto stage = [&](int tt, int bufi) {
        int b = tt >> 9, m0 = (tt & 511) << 2;
        size_t pixbase = ((size_t)(b*MM + m0))*KK;
        int p = g_idx[pixbase + r];
        const char* srcp = (const char*)(g_featsT + ((size_t)(b*PP + p))*CC) + h*64;
        unsigned sdst = abase + (unsigned)(bufi*128*88 + r*88)*2 + h*64;
#pragma unroll
        for (int q = 0; q < 4; q++) cp16(sdst + q*16, srcp + q*16);
        if (h == 0) {
            int m = m0 + (r >> 5);
            const float* xp = xyz + ((size_t)(b*PP + p))*3;
            const float* cpt = centers + ((size_t)(b*MM + m))*3;
            __half2* A2 = (__half2*)(Ab + bufi*128*88);
            A2[r*44 + 32] = __floats2half2_rn(xp[0]-cpt[0], xp[1]-cpt[1]);
            A2[r*44 + 33] = __floats2half2_rn(xp[2]-cpt[2], 0.f);
        }
        CP_COMMIT();
    };

    int tt = blockIdx.x;
    int bufi = 0;
    stage(tt, 0);
    while (tt < NTILES) {
        int nxt = tt + GRID_P;
        if (nxt < NTILES) { stage(nxt, bufi^1); CP_WAIT(1); }
        else CP_WAIT(0);
        __syncthreads();

        const unsigned* Aw = (const unsigned*)(Ab + bufi*128*88);
        int b = tt >> 9, m0 = (tt & 511) << 2;
        size_t pixbase = ((size_t)(b*MM + m0))*KK;

        float acc[4][4][4];
#pragma unroll
        for (int mi = 0; mi < 4; mi++)
#pragma unroll
            for (int ni = 0; ni < 4; ni++) {
                acc[mi][ni][0] = bias0[ni]; acc[mi][ni][1] = bias1[ni];
                acc[mi][ni][2] = bias0[ni]; acc[mi][ni][3] = bias1[ni];
            }
#pragma unroll
        for (int ks = 0; ks < 5; ks++) {
            int kw = ks*8;
            unsigned af[4][4], bf[4][2];
#pragma unroll
            for (int mi = 0; mi < 4; mi++) {
                int rr = warp_pix + mi*16 + g;
                af[mi][0] = Aw[rr*44 + t + kw];
                af[mi][1] = Aw[(rr+8)*44 + t + kw];
                af[mi][2] = Aw[rr*44 + t + 4 + kw];
                af[mi][3] = Aw[(rr+8)*44 + t + 4 + kw];
            }
#pragma unroll
            for (int ni = 0; ni < 4; ni++) {
                int nn = warp_n + ni*8 + g;
                bf[ni][0] = Bw[nn*44 + t + kw];
                bf[ni][1] = Bw[nn*44 + t + 4 + kw];
            }
#pragma unroll
            for (int mi = 0; mi < 4; mi++)
#pragma unroll
                for (int ni = 0; ni < 4; ni++)
                    mma16816(acc[mi][ni], af[mi], bf[ni]);
        }
#pragma unroll
        for (int mi = 0; mi < 4; mi++) {
            int row = warp_pix + mi*16 + g;
#pragma unroll
            for (int ni = 0; ni < 4; ni++) {
                int col = warp_n + ni*8 + 2*t;
                float* a = acc[mi][ni];
                *(__half2*)&g_h0[(pixbase + row)*H1 + col]     = __floats2half2_rn(a[0], a[1]);
                *(__half2*)&g_h0[(pixbase + row + 8)*H1 + col] = __floats2half2_rn(a[2], a[3]);
                ss[ni][0] += a[0] + a[2];  ss[ni][1] += a[1] + a[3];
                sq[ni][0] = fmaf(a[0], a[0], sq[ni][0]);
                sq[ni][0] = fmaf(a[2], a[2], sq[ni][0]);
                sq[ni][1] = fmaf(a[1], a[1], sq[ni][1]);
                sq[ni][1] = fmaf(a[3], a[3], sq[ni][1]);
            }
        }
        __syncthreads();
        bufi ^= 1; tt = nxt;
    }
#pragma unroll
    for (int ni = 0; ni < 4; ni++)
#pragma unroll
        for (int j = 0; j < 2; j++) {
            float s = ss[ni][j], q = sq[ni][j];
            s += __shfl_xor_sync(FULLMASK, s, 4);  q += __shfl_xor_sync(FULLMASK, q, 4);
            s += __shfl_xor_sync(FULLMASK, s, 8);  q += __shfl_xor_sync(FULLMASK, q, 8);
            s += __shfl_xor_sync(FULLMASK, s, 16); q += __shfl_xor_sync(FULLMASK, q, 16);
            if (g == 0) {
                int o = warp_n + ni*8 + 2*t + j;
                atomicAdd(&g_stats1[o], s);
                atomicAdd(&g_stats1[H1 + o], q);
            }
        }
}

// ================= GEMM2: persistent tiles, fused BN1-affine, C staged through smem =================
__global__ void __launch_bounds__(256, 2) k_gemm2(const float* __restrict__ W2,
                                                  const float* __restrict__ b2,
                                                  const float* __restrict__ g1,
                                                  const float* __restrict__ be1) {
    extern __shared__ __half sh[];
    __half* As = sh;                  // 128*136
    __half* Bs = sh + 128*136;
    float* aff1s = (float*)(sh + 2*128*136);
    unsigned* Aw = (unsigned*)As;
    unsigned* Bw = (unsigned*)Bs;
    __half2* Ah2 = (__half2*)As;
    __half2* Bh2 = (__half2*)Bs;

    int tid = threadIdx.x, wid = tid >> 5, lane = tid & 31;
    int g = lane >> 2, t = lane & 3;
    int warp_pix = (wid >> 2) * 64, warp_n = (wid & 3) * 32;
    int r = tid >> 1, h = tid & 1;

    for (int i = tid; i < H1*64; i += 256) {
        int o = i >> 6, wp = i & 63;
        float2 v = ((const float2*)W2)[o*64 + wp];
        Bh2[o*68 + wp] = __floats2half2_rn(v.x, v.y);
    }
    if (tid < H1) {
        float inv = 1.0f / (float)NPIX;
        float mean = g_stats1[tid] * inv;
        float var  = g_stats1[H1 + tid] * inv - mean*mean;
        float a = g1[tid] * rsqrtf(var + BN_EPS);
        aff1s[tid] = a;
        aff1s[H1 + tid] = be1[tid] - a*mean;
    }
    float bias0[4], bias1[4];
#pragma unroll
    for (int ni = 0; ni < 4; ni++) {
        bias0[ni] = b2[warp_n + ni*8 + 2*t];
        bias1[ni] = b2[warp_n + ni*8 + 2*t + 1];
    }

    float ss[4][2], sq[4][2];
#pragma unroll
    for (int ni = 0; ni < 4; ni++) { ss[ni][0]=ss[ni][1]=0.f; sq[ni][0]=sq[ni][1]=0.f; }

    for (int tt = blockIdx.x; tt < NTILES; tt += GRID_P) {
        int b = tt >> 9, m0 = (tt & 511) << 2;
        size_t pixbase = ((size_t)(b*MM + m0))*KK;
        __syncthreads();
        {   // load fp16 h0, bn1+relu fp32, repack fp16
            const uint4* src = (const uint4*)(g_h0 + (pixbase + r)*H1) + h*8;
            int wbase = r*68 + h*32;
#pragma unroll
            for (int q = 0; q < 8; q++) {
                uint4 v = src[q];
                int c = h*64 + q*8;
                const __half2* hv = (const __half2*)&v;
#pragma unroll
                for (int i2 = 0; i2 < 4; i2++) {
                    float2 f = __half22float2(hv[i2]);
                    float2 a = *(const float2*)&aff1s[c + 2*i2];
                    float2 cc = *(const float2*)&aff1s[H1 + c + 2*i2];
                    f.x = fmaxf(fmaf(a.x, f.x, cc.x), 0.f);
                    f.y = fmaxf(fmaf(a.y, f.y, cc.y), 0.f);
                    Ah2[wbase + q*4 + i2] = __floats2half2_rn(f.x, f.y);
                }
            }
        }
        __syncthreads();

        float acc[4][4][4];
#pragma unroll
        for (int mi = 0; mi < 4; mi++)
#pragma unroll
            for (int ni = 0; ni < 4; ni++) {
                acc[mi][ni][0] = bias0[ni]; acc[mi][ni][1] = bias1[ni];
                acc[mi][ni][2] = bias0[ni]; acc[mi][ni][3] = bias1[ni];
            }
#pragma unroll
        for (int ks = 0; ks < 8; ks++) {
            int kw = ks*8;
            unsigned af[4][4], bf[4][2];
#pragma unroll
            for (int mi = 0; mi < 4; mi++) {
                int rr = warp_pix + mi*16 + g;
                af[mi][0] = Aw[rr*68 + t + kw];
                af[mi][1] = Aw[(rr+8)*68 + t + kw];
                af[mi][2] = Aw[rr*68 + t + 4 + kw];
                af[mi][3] = Aw[(rr+8)*68 + t + 4 + kw];
            }
#pragma unroll
            for (int ni = 0; ni < 4; ni++) {
                int nn = warp_n + ni*8 + g;
                bf[ni][0] = Bw[nn*68 + t + kw];
                bf[ni][1] = Bw[nn*68 + t + 4 + kw];
            }
#pragma unroll
            for (int mi = 0; mi < 4; mi++)
#pragma unroll
                for (int ni = 0; ni < 4; ni++)
                    mma16816(acc[mi][ni], af[mi], bf[ni]);
        }

        // stats from registers (order unchanged)
#pragma unroll
        for (int mi = 0; mi < 4; mi++)
#pragma unroll
            for (int ni = 0; ni < 4; ni++) {
                float* a = acc[mi][ni];
                ss[ni][0] += a[0] + a[2];  ss[ni][1] += a[1] + a[3];
                sq[ni][0] = fmaf(a[0], a[0], sq[ni][0]);
                sq[ni][0] = fmaf(a[2], a[2], sq[ni][0]);
                sq[ni][1] = fmaf(a[1], a[1], sq[ni][1]);
                sq[ni][1] = fmaf(a[3], a[3], sq[ni][1]);
            }

        __syncthreads();   // all warps done reading As fragments
        {   // stage C fp16 into As (conflict-free STS), rows 68-word layout
            int wcol = (warp_n >> 1);   // half2 column base
#pragma unroll
            for (int mi = 0; mi < 4; mi++) {
                int row = warp_pix + mi*16 + g;
#pragma unroll
                for (int ni = 0; ni < 4; ni++) {
                    float* a = acc[mi][ni];
                    Ah2[row*68 + wcol + ni*4 + t]     = __floats2half2_rn(a[0], a[1]);
                    Ah2[(row+8)*68 + wcol + ni*4 + t] = __floats2half2_rn(a[2], a[3]);
                }
            }
        }
        __syncthreads();
        {   // coalesced f0 write: full uint4 rows
            const uint4* s = (const uint4*)As + r*17 + h*8;
            uint4* d = (uint4*)(g_f0 + (pixbase + r)*H1) + h*8;
#pragma unroll
            for (int q = 0; q < 8; q++) d[q] = s[q];
        }
    }
#pragma unroll
    for (int ni = 0; ni < 4; ni++)
#pragma unroll
        for (int j = 0; j < 2; j++) {
            float s = ss[ni][j], q = sq[ni][j];
            s += __shfl_xor_sync(FULLMASK, s, 4);  q += __shfl_xor_sync(FULLMASK, q, 4);
            s += __shfl_xor_sync(FULLMASK, s, 8);  q += __shfl_xor_sync(FULLMASK, q, 8);
            s += __shfl_xor_sync(FULLMASK, s, 16); q += __shfl_xor_sync(FULLMASK, q, 16);
            if (g == 0) {
                int o = warp_n + ni*8 + 2*t + j;
                atomicAdd(&g_stats2[o], s);
                atomicAdd(&g_stats2[H1 + o], q);
            }
        }
}

// ================= final: persistent tiles, fused BN2-affine, q-GEMM, softmax, coalesced out ====
__global__ void __launch_bounds__(256, 2) k_final(const float* __restrict__ Wq1,
                                                  const float* __restrict__ bq1,
                                                  const float* __restrict__ Wq2,
                                                  const float* __restrict__ g2,
                                                  const float* __restrict__ be2,
                                                  float* __restrict__ out) {
    extern __shared__ __half sh[];
    __half* As = sh;                  // 128*136
    __half* Bs = sh + 128*136;        // 64*136
    float* aff2s = (float*)(sh + 128*136 + 64*136);
    float* bq1s  = aff2s + 2*H1;
    float* wq2s  = bq1s + Q1;
    float* slog0 = wq2s + Q1;
    float* slog1 = slog0 + 128;
    float* wk    = slog1 + 128;
    float* outb  = wk + 128;          // 512 floats: [mm][o]
    unsigned* Aw = (unsigned*)As;
    unsigned* Bw = (unsigned*)Bs;
    __half2* Ah2 = (__half2*)As;
    __half2* Bh2 = (__half2*)Bs;

    int tid = threadIdx.x, wid = tid >> 5, lane = tid & 31;
    int g = lane >> 2, t = lane & 3;
    int warp_pix = (wid & 3) * 32, warp_n = (wid >> 2) * 32;
    int r = tid >> 1, h = tid & 1;

    for (int i = tid; i < Q1*64; i += 256) {
        int n = i >> 6, wp = i & 63;
        float2 v = ((const float2*)Wq1)[n*64 + wp];
        Bh2[n*68 + wp] = __floats2half2_rn(v.x, v.y);
    }
    if (tid < H1) {
        float inv = 1.0f / (float)NPIX;
        float mean = g_stats2[tid] * inv;
        float var  = g_stats2[H1 + tid] * inv - mean*mean;
        float a = g2[tid] * rsqrtf(var + BN_EPS);
        aff2s[tid] = a;
        aff2s[H1 + tid] = be2[tid] - a*mean;
    }
    if (tid < Q1) { bq1s[tid] = bq1[tid]; wq2s[tid] = Wq2[tid]; }

    float bias0[4], bias1[4], w20[4], w21[4];
    __syncthreads();
#pragma unroll
    for (int ni = 0; ni < 4; ni++) {
        bias0[ni] = bq1s[warp_n + ni*8 + 2*t];
        bias1[ni] = bq1s[warp_n + ni*8 + 2*t + 1];
        w20[ni]   = wq2s[warp_n + ni*8 + 2*t];
        w21[ni]   = wq2s[warp_n + ni*8 + 2*t + 1];
    }

    for (int tt = blockIdx.x; tt < NTILES; tt += GRID_P) {
        int b = tt >> 9, m0 = (tt & 511) << 2;
        size_t pixbase = ((size_t)(b*MM + m0))*KK;
        size_t obase = (size_t)BB*MM*3 + (size_t)b*H1*MM;
        __syncthreads();
        {   // load fp16 f0, bn2+relu fp32 math, repack fp16
            const uint4* src = (const uint4*)(g_f0 + (pixbase + r)*H1) + h*8;
            int wbase = r*68 + h*32;
#pragma unroll
            for (int q = 0; q < 8; q++) {
                uint4 v = src[q];
                int c = h*64 + q*8;
                const __half2* hv = (const __half2*)&v;
#pragma unroll
                for (int i2 = 0; i2 < 4; i2++) {
                    float2 f = __half22float2(hv[i2]);
                    float2 a = *(const float2*)&aff2s[c + 2*i2];
                    float2 cc = *(const float2*)&aff2s[H1 + c + 2*i2];
                    f.x = fmaxf(fmaf(a.x, f.x, cc.x), 0.f);
                    f.y = fmaxf(fmaf(a.y, f.y, cc.y), 0.f);
                    Ah2[wbase + q*4 + i2] = __floats2half2_rn(f.x, f.y);
                }
            }
        }
        __syncthreads();

        float acc[2][4][4];
#pragma unroll
        for (int mi = 0; mi < 2; mi++)
#pragma unroll
            for (int ni = 0; ni < 4; ni++) {
                acc[mi][ni][0] = bias0[ni]; acc[mi][ni][1] = bias1[ni];
                acc[mi][ni][2] = bias0[ni]; acc[mi][ni][3] = bias1[ni];
            }
#pragma unroll
        for (int ks = 0; ks < 8; ks++) {
            int kw = ks*8;
            unsigned af[2][4], bf[4][2];
#pragma unroll
            for (int mi = 0; mi < 2; mi++) {
                int rr = warp_pix + mi*16 + g;
                af[mi][0] = Aw[rr*68 + t + kw];
                af[mi][1] = Aw[(rr+8)*68 + t + kw];
                af[mi][2] = Aw[rr*68 + t + 4 + kw];
                af[mi][3] = Aw[(rr+8)*68 + t + 4 + kw];
            }
#pragma unroll
            for (int ni = 0; ni < 4; ni++) {
                int nn = warp_n + ni*8 + g;
                bf[ni][0] = Bw[nn*68 + t + kw];
                bf[ni][1] = Bw[nn*68 + t + 4 + kw];
            }
#pragma unroll
            for (int mi = 0; mi < 2; mi++)
#pragma unroll
                for (int ni = 0; ni < 4; ni++)
                    mma16816(acc[mi][ni], af[mi], bf[ni]);
        }

        // logits partial: s(pix) = sum_j wq2[j] * relu(q_j)
        float* sl = (wid < 4) ? slog0 : slog1;
#pragma unroll
        for (int mi = 0; mi < 2; mi++) {
            float p0 = 0.f, p1 = 0.f;
#pragma unroll
            for (int ni = 0; ni < 4; ni++) {
                float* a = acc[mi][ni];
                p0 = fmaf(w20[ni], fmaxf(a[0], 0.f), p0);
                p0 = fmaf(w21[ni], fmaxf(a[1], 0.f), p0);
                p1 = fmaf(w20[ni], fmaxf(a[2], 0.f), p1);
                p1 = fmaf(w21[ni], fmaxf(a[3], 0.f), p1);
            }
            p0 += __shfl_xor_sync(FULLMASK, p0, 1);
            p0 += __shfl_xor_sync(FULLMASK, p0, 2);
            p1 += __shfl_xor_sync(FULLMASK, p1, 1);
            p1 += __shfl_xor_sync(FULLMASK, p1, 2);
            if (t == 0) {
                sl[warp_pix + mi*16 + g]     = p0;
                sl[warp_pix + mi*16 + 8 + g] = p1;
            }
        }
        __syncthreads();
        if (wid < 4) {   // softmax per m over 32 neighbors (bq2 shift-invariant)
            int idx = wid*32 + lane;
            float s = slog0[idx] + slog1[idx];
            float mx = s;
#pragma unroll
            for (int off = 16; off; off >>= 1)
                mx = fmaxf(mx, __shfl_xor_sync(FULLMASK, mx, off));
            float e = expf(s - mx);
            float sum = e;
#pragma unroll
            for (int off = 16; off; off >>= 1)
                sum += __shfl_xor_sync(FULLMASK, sum, off);
            wk[idx] = e / sum;
        }
        __syncthreads();
        {   // aggregate into smem (same accumulation order), then coalesced out
            int o = tid & 127, mh = tid >> 7;
#pragma unroll
            for (int mm0 = 0; mm0 < 2; mm0++) {
                int mm = mh + mm0*2;
                float a = 0.f;
#pragma unroll
                for (int kn = 0; kn < 32; kn++)
                    a = fmaf(__half2float(As[(mm*32 + kn)*136 + o]), wk[mm*32 + kn], a);
                outb[mm*128 + o] = a;
            }
        }
        __syncthreads();
        if (tid < 128) {
            float4 v;
            v.x = outb[0*128 + tid];
            v.y = outb[1*128 + tid];
            v.z = outb[2*128 + tid];
            v.w = outb[3*128 + tid];
            *(float4*)&out[obase + (size_t)tid*MM + m0] = v;
        }
    }
}

// ---------------- launch ----------------
extern "C" void kernel_launch(void* const* d_in, const int* in_sizes, int n_in,
                              void* d_out, int out_size) {
    const float* xyz  = (const float*)d_in[0];
    const float* feats= (const float*)d_in[1];
    const float* W1   = (const float*)d_in[2];
    const float* b1   = (const float*)d_in[3];
    const float* g1   = (const float*)d_in[4];
    const float* be1  = (const float*)d_in[5];
    const float* W2   = (const float*)d_in[6];
    const float* b2   = (const float*)d_in[7];
    const float* g2   = (const float*)d_in[8];
    const float* be2  = (const float*)d_in[9];
    const float* Wq1  = (const float*)d_in[10];
    const float* bq1  = (const float*)d_in[11];
    const float* Wq2  = (const float*)d_in[12];
    float* out = (float*)d_out;

    void *idxp;
    cudaGetSymbolAddress(&idxp, g_idx);

    const int smem1 = (2*128*88 + 128*88)*2;                                // 67584 B
    const int smem2 = 2*128*136*2 + 2*H1*4;                                 // 70656 B
    const int smem3 = (128*136 + 64*136)*2 + (2*H1 + 2*Q1 + 3*128 + 512)*4; // 57344 B

    cudaFuncSetAttribute(k_gemm1, cudaFuncAttributeMaxDynamicSharedMemorySize, smem1);
    cudaFuncSetAttribute(k_gemm2, cudaFuncAttributeMaxDynamicSharedMemorySize, smem2);
    cudaFuncSetAttribute(k_final, cudaFuncAttributeMaxDynamicSharedMemorySize, smem3);

    k_knn<<<BB*MM/16, 256>>>(xyz, feats, out, (int*)idxp);
    k_gemm1<<<GRID_P, 256, smem1>>>(xyz, out, W1, b1);
    k_gemm2<<<GRID_P, 256, smem2>>>(W2, b2, g1, be1);
    k_final<<<GRID_P, 256, smem3>>>(Wq1, bq1, Wq2, g2, be2, out);
}

// round 15
// speedup vs baseline: 1.0316x; 1.0316x over previous
#include <cuda_runtime.h>
#include <cuda_fp16.h>
#include <math.h>
#include <float.h>

#define BB 4
#define PP 8192
#define CC 64
#define MM 2048
#define KK 32
#define CIN 67
#define H1 128
#define Q1 64
#define NPIX (BB*MM*KK)
#define BN_EPS 1e-5f
#define FULLMASK 0xffffffffu
#define NTILES 2048
#define GRID_P 296

// ---------------- scratch (fp16 intermediates) ----------------
__device__ __half g_featsT[(size_t)BB*PP*CC];
__device__ int    g_idx[(size_t)BB*MM*KK];
__device__ __half g_h0[(size_t)NPIX*H1];
__device__ __half g_f0[(size_t)NPIX*H1];
__device__ float  g_stats1[2*H1];
__device__ float  g_stats2[2*H1];

// ---------------- helpers ----------------
__device__ __forceinline__ void mma16816(float* c, const unsigned* a, const unsigned* b) {
    asm volatile(
        "mma.sync.aligned.m16n8k16.row.col.f32.f16.f16.f32 "
        "{%0,%1,%2,%3}, {%4,%5,%6,%7}, {%8,%9}, {%0,%1,%2,%3};"
        : "+f"(c[0]), "+f"(c[1]), "+f"(c[2]), "+f"(c[3])
        : "r"(a[0]), "r"(a[1]), "r"(a[2]), "r"(a[3]), "r"(b[0]), "r"(b[1]));
}
__device__ __forceinline__ void cp16(unsigned dst, const void* src) {
    asm volatile("cp.async.ca.shared.global [%0], [%1], 16;\n" :: "r"(dst), "l"(src));
}
#define CP_COMMIT() asm volatile("cp.async.commit_group;\n" ::: "memory")
#define CP_WAIT(n)  asm volatile("cp.async.wait_group %0;\n" :: "n"(n) : "memory")

// ---------------- KNN (+ fused feats transpose, centers, stats zeroing) ----------------
__global__ void __launch_bounds__(256) k_knn(const float* __restrict__ xyz,
                                             const float* __restrict__ feats,
                                             float* __restrict__ out,
                                             int* __restrict__ idxout) {
    int tid = threadIdx.x;

    {   // fused pre: transpose feats (B,C,P) -> featsT (B,P,C) fp16, 64 rows/block
        int row0 = blockIdx.x * 64;
        for (int i = tid; i < 64*32; i += 256) {
            int row = row0 + (i & 63);
            int cp  = i >> 6;
            int b = row >> 13;
            int p = row & (PP-1);
            const float* s = feats + (size_t)b*CC*PP + (size_t)(2*cp)*PP + p;
            ((__half2*)(g_featsT + (size_t)row*CC))[cp] = __floats2half2_rn(s[0], s[PP]);
        }
    }
    if (blockIdx.x == 0 && tid < 2*H1) {
        g_stats1[tid] = 0.f;
        g_stats2[tid] = 0.f;
    }

    int c0   = (blockIdx.x * 8 + (tid >> 5)) * 2;
    int lane = tid & 31;
    int b    = c0 >> 11;
    float cx[2], cy[2], cz[2], cc2[2];
#pragma unroll
    for (int jj = 0; jj < 2; jj++) {
        int ci = c0 + jj;
        int m  = ci & (MM-1);
        int pc;
        if (m == MM-1) pc = PP-1;
        else {
            float t = __fdiv_rn((float)m, (float)(MM-1));
            float v = __fmul_rn((float)(PP-1), t);
            pc = (int)v;
            if (pc > PP-1) pc = PP-1;
        }
        const float* s = xyz + ((size_t)(b*PP + pc))*3;
        cx[jj] = s[0]; cy[jj] = s[1]; cz[jj] = s[2];
        cc2[jj] = cx[jj]*cx[jj] + cy[jj]*cy[jj] + cz[jj]*cz[jj];
        if (lane == jj) {
            out[(size_t)ci*3 + 0] = cx[jj];
            out[(size_t)ci*3 + 1] = cy[jj];
            out[(size_t)ci*3 + 2] = cz[jj];
        }
    }
    const float* xb = xyz + (size_t)b*PP*3;

    float ld[2] = {FLT_MAX, FLT_MAX};
    int   li[2] = {0x7fffffff, 0x7fffffff};
    float kth[2] = {FLT_MAX, FLT_MAX};

    for (int base = 0; base < PP; base += 32) {
        int p = base + lane;
        float x = xb[3*p], y = xb[3*p+1], z = xb[3*p+2];
        float x2 = x*x + y*y + z*z;
#pragma unroll
        for (int jj = 0; jj < 2; jj++) {
            float d = (cc2[jj] + x2) - 2.0f*(cx[jj]*x + cy[jj]*y + cz[jj]*z);
            unsigned mask = __ballot_sync(FULLMASK, d < kth[jj]);
            while (mask) {
                int j = __ffs(mask) - 1; mask &= mask - 1;
                float dj = __shfl_sync(FULLMASK, d, j);
                if (dj < kth[jj]) {
                    int pj = base + j;
                    unsigned lt = __ballot_sync(FULLMASK,
                        (ld[jj] < dj) || (ld[jj] == dj && li[jj] < pj));
                    int pos = __popc(lt);
                    float pd = __shfl_up_sync(FULLMASK, ld[jj], 1);
                    int   pi = __shfl_up_sync(FULLMASK, li[jj], 1);
                    if (lane == pos)      { ld[jj] = dj; li[jj] = pj; }
                    else if (lane > pos)  { ld[jj] = pd; li[jj] = pi; }
                    kth[jj] = __shfl_sync(FULLMASK, ld[jj], 31);
                }
            }
        }
    }
#pragma unroll
    for (int jj = 0; jj < 2; jj++)
        idxout[(size_t)(c0 + jj)*KK + lane] = li[jj];
}

// ================= GEMM1: persistent tiles, cp.async double-buffered gather + MMA =================
__global__ void __launch_bounds__(256, 2) k_gemm1(const float* __restrict__ xyz,
                                                  const float* __restrict__ centers,
                                                  const float* __restrict__ W1,
                                                  const float* __restrict__ b1) {
    extern __shared__ __half sh[];
    __half* Ab = sh;                       // 2 * 128*88
    __half* Bs = sh + 2*128*88;
    unsigned* Bw = (unsigned*)Bs;

    int tid = threadIdx.x, wid = tid >> 5, lane = tid & 31;
    int g = lane >> 2, t = lane & 3;
    int warp_pix = (wid >> 2) * 64, warp_n = (wid & 3) * 32;
    int r = tid >> 1, h = tid & 1;

    for (int i = tid; i < 128*44; i += 256) Bw[i] = 0u;
    {
        __half z = __float2half_rn(0.f);
#pragma unroll
        for (int bufi = 0; bufi < 2; bufi++)
            if (h == 1)
                for (int q = 64; q < 88; q++) Ab[bufi*128*88 + r*88 + q] = z;
    }
    __syncthreads();
    for (int i = tid; i < H1*CIN; i += 256) {
        int o = i / CIN, c = i - o*CIN;
        int col = (c < 3) ? (64 + c) : (c - 3);
        Bs[o*88 + col] = __float2half_rn(W1[i]);
    }
    float bias0[4], bias1[4];
#pragma unroll
    for (int ni = 0; ni < 4; ni++) {
        bias0[ni] = b1[warp_n + ni*8 + 2*t];
        bias1[ni] = b1[warp_n + ni*8 + 2*t + 1];
    }
    unsigned abase = (unsigned)__cvta_generic_to_shared(Ab);

    float ss[4][2], sq[4][2];
#pragma unroll
    for (int ni = 0; ni < 4; ni++) { ss[ni][0]=ss[ni][1]=0.f; sq[ni][0]=sq[ni][1]=0.f; }

    auto stage = [&](int tt, int bufi) {
        int b = tt >> 9, m0 = (tt & 511) << 2;
        size_t pixbase = ((size_t)(b*MM + m0))*KK;
        int p = g_idx[pixbase + r];
        const char* srcp = (const char*)(g_featsT + ((size_t)(b*PP + p))*CC) + h*64;
        unsigned sdst = abase + (unsigned)(bufi*128*88 + r*88)*2 + h*64;
#pragma unroll
        for (int q = 0; q < 4; q++) cp16(sdst + q*16, srcp + q*16);
        if (h == 0) {
            int m = m0 + (r >> 5);
            const float* xp = xyz + ((size_t)(b*PP + p))*3;
            const float* cpt = centers + ((size_t)(b*MM + m))*3;
            __half2* A2 = (__half2*)(Ab + bufi*128*88);
            A2[r*44 + 32] = __floats2half2_rn(xp[0]-cpt[0], xp[1]-cpt[1]);
            A2[r*44 + 33] = __floats2half2_rn(xp[2]-cpt[2], 0.f);
        }
        CP_COMMIT();
    };

    int tt = blockIdx.x;
    int bufi = 0;
    stage(tt, 0);
    while (tt < NTILES) {
        int nxt = tt + GRID_P;
        if (nxt < NTILES) { stage(nxt, bufi^1); CP_WAIT(1); }
        else CP_WAIT(0);
        __syncthreads();

        const unsigned* Aw = (const unsigned*)(Ab + bufi*128*88);
        int b = tt >> 9, m0 = (tt & 511) << 2;
        size_t pixbase = ((size_t)(b*MM + m0))*KK;

        float acc[4][4][4];
#pragma unroll
        for (int mi = 0; mi < 4; mi++)
#pragma unroll
            for (int ni = 0; ni < 4; ni++) {
                acc[mi][ni][0] = bias0[ni]; acc[mi][ni][1] = bias1[ni];
                acc[mi][ni][2] = bias0[ni]; acc[mi][ni][3] = bias1[ni];
            }
#pragma unroll
        for (int ks = 0; ks < 5; ks++) {
            int kw = ks*8;
            unsigned af[4][4], bf[4][2];
#pragma unroll
            for (int mi = 0; mi < 4; mi++) {
                int rr = warp_pix + mi*16 + g;
                af[mi][0] = Aw[rr*44 + t + kw];
                af[mi][1] = Aw[(rr+8)*44 + t + kw];
                af[mi][2] = Aw[rr*44 + t + 4 + kw];
                af[mi][3] = Aw[(rr+8)*44 + t + 4 + kw];
            }
#pragma unroll
            for (int ni = 0; ni < 4; ni++) {
                int nn = warp_n + ni*8 + g;
                bf[ni][0] = Bw[nn*44 + t + kw];
                bf[ni][1] = Bw[nn*44 + t + 4 + kw];
            }
#pragma unroll
            for (int mi = 0; mi < 4; mi++)
#pragma unroll
                for (int ni = 0; ni < 4; ni++)
                    mma16816(acc[mi][ni], af[mi], bf[ni]);
        }
#pragma unroll
        for (int mi = 0; mi < 4; mi++) {
            int row = warp_pix + mi*16 + g;
#pragma unroll
            for (int ni = 0; ni < 4; ni++) {
                int col = warp_n + ni*8 + 2*t;
                float* a = acc[mi][ni];
                *(__half2*)&g_h0[(pixbase + row)*H1 + col]     = __floats2half2_rn(a[0], a[1]);
                *(__half2*)&g_h0[(pixbase + row + 8)*H1 + col] = __floats2half2_rn(a[2], a[3]);
                ss[ni][0] += a[0] + a[2];  ss[ni][1] += a[1] + a[3];
                sq[ni][0] = fmaf(a[0], a[0], sq[ni][0]);
                sq[ni][0] = fmaf(a[2], a[2], sq[ni][0]);
                sq[ni][1] = fmaf(a[1], a[1], sq[ni][1]);
                sq[ni][1] = fmaf(a[3], a[3], sq[ni][1]);
            }
        }
        __syncthreads();
        bufi ^= 1; tt = nxt;
    }
#pragma unroll
    for (int ni = 0; ni < 4; ni++)
#pragma unroll
        for (int j = 0; j < 2; j++) {
            float s = ss[ni][j], q = sq[ni][j];
            s += __shfl_xor_sync(FULLMASK, s, 4);  q += __shfl_xor_sync(FULLMASK, q, 4);
            s += __shfl_xor_sync(FULLMASK, s, 8);  q += __shfl_xor_sync(FULLMASK, q, 8);
            s += __shfl_xor_sync(FULLMASK, s, 16); q += __shfl_xor_sync(FULLMASK, q, 16);
            if (g == 0) {
                int o = warp_n + ni*8 + 2*t + j;
                atomicAdd(&g_stats1[o], s);
                atomicAdd(&g_stats1[H1 + o], q);
            }
        }
}

// ================= GEMM2: persistent tiles, fused BN1-affine (R12 epilogue) =================
__global__ void __launch_bounds__(256, 2) k_gemm2(const float* __restrict__ W2,
                                                  const float* __restrict__ b2,
                                                  const float* __restrict__ g1,
                                                  const float* __restrict__ be1) {
    extern __shared__ __half sh[];
    __half* As = sh;                  // 128*136
    __half* Bs = sh + 128*136;
    float* aff1s = (float*)(sh + 2*128*136);
    unsigned* Aw = (unsigned*)As;
    unsigned* Bw = (unsigned*)Bs;
    __half2* Ah2 = (__half2*)As;
    __half2* Bh2 = (__half2*)Bs;

    int tid = threadIdx.x, wid = tid >> 5, lane = tid & 31;
    int g = lane >> 2, t = lane & 3;
    int warp_pix = (wid >> 2) * 64, warp_n = (wid & 3) * 32;
    int r = tid >> 1, h = tid & 1;

    for (int i = tid; i < H1*64; i += 256) {
        int o = i >> 6, wp = i & 63;
        float2 v = ((const float2*)W2)[o*64 + wp];
        Bh2[o*68 + wp] = __floats2half2_rn(v.x, v.y);
    }
    if (tid < H1) {
        float inv = 1.0f / (float)NPIX;
        float mean = g_stats1[tid] * inv;
        float var  = g_stats1[H1 + tid] * inv - mean*mean;
        float a = g1[tid] * rsqrtf(var + BN_EPS);
        aff1s[tid] = a;
        aff1s[H1 + tid] = be1[tid] - a*mean;
    }
    float bias0[4], bias1[4];
#pragma unroll
    for (int ni = 0; ni < 4; ni++) {
        bias0[ni] = b2[warp_n + ni*8 + 2*t];
        bias1[ni] = b2[warp_n + ni*8 + 2*t + 1];
    }

    float ss[4][2], sq[4][2];
#pragma unroll
    for (int ni = 0; ni < 4; ni++) { ss[ni][0]=ss[ni][1]=0.f; sq[ni][0]=sq[ni][1]=0.f; }

    for (int tt = blockIdx.x; tt < NTILES; tt += GRID_P) {
        int b = tt >> 9, m0 = (tt & 511) << 2;
        size_t pixbase = ((size_t)(b*MM + m0))*KK;
        __syncthreads();
        {   // load fp16 h0, bn1+relu fp32, repack fp16
            const uint4* src = (const uint4*)(g_h0 + (pixbase + r)*H1) + h*8;
            int wbase = r*68 + h*32;
#pragma unroll
            for (int q = 0; q < 8; q++) {
                uint4 v = src[q];
                int c = h*64 + q*8;
                const __half2* hv = (const __half2*)&v;
#pragma unroll
                for (int i2 = 0; i2 < 4; i2++) {
                    float2 f = __half22float2(hv[i2]);
                    float2 a = *(const float2*)&aff1s[c + 2*i2];
                    float2 cc = *(const float2*)&aff1s[H1 + c + 2*i2];
                    f.x = fmaxf(fmaf(a.x, f.x, cc.x), 0.f);
                    f.y = fmaxf(fmaf(a.y, f.y, cc.y), 0.f);
                    Ah2[wbase + q*4 + i2] = __floats2half2_rn(f.x, f.y);
                }
            }
        }
        __syncthreads();

        float acc[4][4][4];
#pragma unroll
        for (int mi = 0; mi < 4; mi++)
#pragma unroll
            for (int ni = 0; ni < 4; ni++) {
                acc[mi][ni][0] = bias0[ni]; acc[mi][ni][1] = bias1[ni];
                acc[mi][ni][2] = bias0[ni]; acc[mi][ni][3] = bias1[ni];
            }
#pragma unroll
        for (int ks = 0; ks < 8; ks++) {
            int kw = ks*8;
            unsigned af[4][4], bf[4][2];
#pragma unroll
            for (int mi = 0; mi < 4; mi++) {
                int rr = warp_pix + mi*16 + g;
                af[mi][0] = Aw[rr*68 + t + kw];
                af[mi][1] = Aw[(rr+8)*68 + t + kw];
                af[mi][2] = Aw[rr*68 + t + 4 + kw];
                af[mi][3] = Aw[(rr+8)*68 + t + 4 + kw];
            }
#pragma unroll
            for (int ni = 0; ni < 4; ni++) {
                int nn = warp_n + ni*8 + g;
                bf[ni][0] = Bw[nn*68 + t + kw];
                bf[ni][1] = Bw[nn*68 + t + 4 + kw];
            }
#pragma unroll
            for (int mi = 0; mi < 4; mi++)
#pragma unroll
                for (int ni = 0; ni < 4; ni++)
                    mma16816(acc[mi][ni], af[mi], bf[ni]);
        }
#pragma unroll
        for (int mi = 0; mi < 4; mi++) {
            int row = warp_pix + mi*16 + g;
#pragma unroll
            for (int ni = 0; ni < 4; ni++) {
                int col = warp_n + ni*8 + 2*t;
                float* a = acc[mi][ni];
                *(__half2*)&g_f0[(pixbase + row)*H1 + col]     = __floats2half2_rn(a[0], a[1]);
                *(__half2*)&g_f0[(pixbase + row + 8)*H1 + col] = __floats2half2_rn(a[2], a[3]);
                ss[ni][0] += a[0] + a[2];  ss[ni][1] += a[1] + a[3];
                sq[ni][0] = fmaf(a[0], a[0], sq[ni][0]);
                sq[ni][0] = fmaf(a[2], a[2], sq[ni][0]);
                sq[ni][1] = fmaf(a[1], a[1], sq[ni][1]);
                sq[ni][1] = fmaf(a[3], a[3], sq[ni][1]);
            }
        }
    }
#pragma unroll
    for (int ni = 0; ni < 4; ni++)
#pragma unroll
        for (int j = 0; j < 2; j++) {
            float s = ss[ni][j], q = sq[ni][j];
            s += __shfl_xor_sync(FULLMASK, s, 4);  q += __shfl_xor_sync(FULLMASK, q, 4);
            s += __shfl_xor_sync(FULLMASK, s, 8);  q += __shfl_xor_sync(FULLMASK, q, 8);
            s += __shfl_xor_sync(FULLMASK, s, 16); q += __shfl_xor_sync(FULLMASK, q, 16);
            if (g == 0) {
                int o = warp_n + ni*8 + 2*t + j;
                atomicAdd(&g_stats2[o], s);
                atomicAdd(&g_stats2[H1 + o], q);
            }
        }
}

// ================= final: persistent tiles, fused BN2-affine, q-GEMM, softmax, coalesced out ====
__global__ void __launch_bounds__(256, 2) k_final(const float* __restrict__ Wq1,
                                                  const float* __restrict__ bq1,
                                                  const float* __restrict__ Wq2,
                                                  const float* __restrict__ g2,
                                                  const float* __restrict__ be2,
                                                  float* __restrict__ out) {
    extern __shared__ __half sh[];
    __half* As = sh;                  // 128*136
    __half* Bs = sh + 128*136;        // 64*136
    float* aff2s = (float*)(sh + 128*136 + 64*136);
    float* bq1s  = aff2s + 2*H1;
    float* wq2s  = bq1s + Q1;
    float* slog0 = wq2s + Q1;
    float* slog1 = slog0 + 128;
    float* wk    = slog1 + 128;
    float* outb  = wk + 128;          // 512 floats: [mm][o]
    unsigned* Aw = (unsigned*)As;
    unsigned* Bw = (unsigned*)Bs;
    __half2* Ah2 = (__half2*)As;
    __half2* Bh2 = (__half2*)Bs;

    int tid = threadIdx.x, wid = tid >> 5, lane = tid & 31;
    int g = lane >> 2, t = lane & 3;
    int warp_pix = (wid & 3) * 32, warp_n = (wid >> 2) * 32;
    int r = tid >> 1, h = tid & 1;

    for (int i = tid; i < Q1*64; i += 256) {
        int n = i >> 6, wp = i & 63;
        float2 v = ((const float2*)Wq1)[n*64 + wp];
        Bh2[n*68 + wp] = __floats2half2_rn(v.x, v.y);
    }
    if (tid < H1) {
        float inv = 1.0f / (float)NPIX;
        float mean = g_stats2[tid] * inv;
        float var  = g_stats2[H1 + tid] * inv - mean*mean;
        float a = g2[tid] * rsqrtf(var + BN_EPS);
        aff2s[tid] = a;
        aff2s[H1 + tid] = be2[tid] - a*mean;
    }
    if (tid < Q1) { bq1s[tid] = bq1[tid]; wq2s[tid] = Wq2[tid]; }

    float bias0[4], bias1[4], w20[4], w21[4];
    __syncthreads();
#pragma unroll
    for (int ni = 0; ni < 4; ni++) {
        bias0[ni] = bq1s[warp_n + ni*8 + 2*t];
        bias1[ni] = bq1s[warp_n + ni*8 + 2*t + 1];
        w20[ni]   = wq2s[warp_n + ni*8 + 2*t];
        w21[ni]   = wq2s[warp_n + ni*8 + 2*t + 1];
    }

    for (int tt = blockIdx.x; tt < NTILES; tt += GRID_P) {
        int b = tt >> 9, m0 = (tt & 511) << 2;
        size_t pixbase = ((size_t)(b*MM + m0))*KK;
        size_t obase = (size_t)BB*MM*3 + (size_t)b*H1*MM;
        __syncthreads();
        {   // load fp16 f0, bn2+relu fp32 math, repack fp16
            const uint4* src = (const uint4*)(g_f0 + (pixbase + r)*H1) + h*8;
            int wbase = r*68 + h*32;
#pragma unroll
            for (int q = 0; q < 8; q++) {
                uint4 v = src[q];
                int c = h*64 + q*8;
                const __half2* hv = (const __half2*)&v;
#pragma unroll
                for (int i2 = 0; i2 < 4; i2++) {
                    float2 f = __half22float2(hv[i2]);
                    float2 a = *(const float2*)&aff2s[c + 2*i2];
                    float2 cc = *(const float2*)&aff2s[H1 + c + 2*i2];
                    f.x = fmaxf(fmaf(a.x, f.x, cc.x), 0.f);
                    f.y = fmaxf(fmaf(a.y, f.y, cc.y), 0.f);
                    Ah2[wbase + q*4 + i2] = __floats2half2_rn(f.x, f.y);
                }
            }
        }
        __syncthreads();

        float acc[2][4][4];
#pragma unroll
        for (int mi = 0; mi < 2; mi++)
#pragma unroll
            for (int ni = 0; ni < 4; ni++) {
                acc[mi][ni][0] = bias0[ni]; acc[mi][ni][1] = bias1[ni];
                acc[mi][ni][2] = bias0[ni]; acc[mi][ni][3] = bias1[ni];
            }
#pragma unroll
        for (int ks = 0; ks < 8; ks++) {
            int kw = ks*8;
            unsigned af[2][4], bf[4][2];
#pragma unroll
            for (int mi = 0; mi < 2; mi++) {
                int rr = warp_pix + mi*16 + g;
                af[mi][0] = Aw[rr*68 + t + kw];
                af[mi][1] = Aw[(rr+8)*68 + t + kw];
                af[mi][2] = Aw[rr*68 + t + 4 + kw];
                af[mi][3] = Aw[(rr+8)*68 + t + 4 + kw];
            }
#pragma unroll
            for (int ni = 0; ni < 4; ni++) {
                int nn = warp_n + ni*8 + g;
                bf[ni][0] = Bw[nn*68 + t + kw];
                bf[ni][1] = Bw[nn*68 + t + 4 + kw];
            }
#pragma unroll
            for (int mi = 0; mi < 2; mi++)
#pragma unroll
                for (int ni = 0; ni < 4; ni++)
                    mma16816(acc[mi][ni], af[mi], bf[ni]);
        }

        // logits partial: s(pix) = sum_j wq2[j] * relu(q_j)
        float* sl = (wid < 4) ? slog0 : slog1;
#pragma unroll
        for (int mi = 0; mi < 2; mi++) {
            float p0 = 0.f, p1 = 0.f;
#pragma unroll
            for (int ni = 0; ni < 4; ni++) {
                float* a = acc[mi][ni];
                p0 = fmaf(w20[ni], fmaxf(a[0], 0.f), p0);
                p0 = fmaf(w21[ni], fmaxf(a[1], 0.f), p0);
                p1 = fmaf(w20[ni], fmaxf(a[2], 0.f), p1);
                p1 = fmaf(w21[ni], fmaxf(a[3], 0.f), p1);
            }
            p0 += __shfl_xor_sync(FULLMASK, p0, 1);
            p0 += __shfl_xor_sync(FULLMASK, p0, 2);
            p1 += __shfl_xor_sync(FULLMASK, p1, 1);
            p1 += __shfl_xor_sync(FULLMASK, p1, 2);
            if (t == 0) {
                sl[warp_pix + mi*16 + g]     = p0;
                sl[warp_pix + mi*16 + 8 + g] = p1;
            }
        }
        __syncthreads();
        if (wid < 4) {   // softmax per m over 32 neighbors (bq2 shift-invariant)
            int idx = wid*32 + lane;
            float s = slog0[idx] + slog1[idx];
            float mx = s;
#pragma unroll
            for (int off = 16; off; off >>= 1)
                mx = fmaxf(mx, __shfl_xor_sync(FULLMASK, mx, off));
            float e = expf(s - mx);
            float sum = e;
#pragma unroll
            for (int off = 16; off; off >>= 1)
                sum += __shfl_xor_sync(FULLMASK, sum, off);
            wk[idx] = e / sum;
        }
        __syncthreads();
        {   // aggregate via half2 reads (same per-element accumulation order), then coalesced out
            int o2 = tid & 63, mm = tid >> 6;     // o pair = {2*o2, 2*o2+1}, one mm per thread
            float a0 = 0.f, a1 = 0.f;
#pragma unroll
            for (int kn = 0; kn < 32; kn++) {
                float2 f = __half22float2(Ah2[(mm*32 + kn)*68 + o2]);
                float w = wk[mm*32 + kn];
                a0 = fmaf(f.x, w, a0);
                a1 = fmaf(f.y, w, a1);
            }
            outb[mm*128 + 2*o2]     = a0;
            outb[mm*128 + 2*o2 + 1] = a1;
        }
        __syncthreads();
        if (tid < 128) {
            float4 v;
            v.x = outb[0*128 + tid];
            v.y = outb[1*128 + tid];
            v.z = outb[2*128 + tid];
            v.w = outb[3*128 + tid];
            *(float4*)&out[obase + (size_t)tid*MM + m0] = v;
        }
    }
}

// ---------------- launch ----------------
extern "C" void kernel_launch(void* const* d_in, const int* in_sizes, int n_in,
                              void* d_out, int out_size) {
    const float* xyz  = (const float*)d_in[0];
    const float* feats= (const float*)d_in[1];
    const float* W1   = (const float*)d_in[2];
    const float* b1   = (const float*)d_in[3];
    const float* g1   = (const float*)d_in[4];
    const float* be1  = (const float*)d_in[5];
    const float* W2   = (const float*)d_in[6];
    const float* b2   = (const float*)d_in[7];
    const float* g2   = (const float*)d_in[8];
    const float* be2  = (const float*)d_in[9];
    const float* Wq1  = (const float*)d_in[10];
    const float* bq1  = (const float*)d_in[11];
    const float* Wq2  = (const float*)d_in[12];
    float* out = (float*)d_out;

    void *idxp;
    cudaGetSymbolAddress(&idxp, g_idx);

    const int smem1 = (2*128*88 + 128*88)*2;                                // 67584 B
    const int smem2 = 2*128*136*2 + 2*H1*4;                                 // 70656 B
    const int smem3 = (128*136 + 64*136)*2 + (2*H1 + 2*Q1 + 3*128 + 512)*4; // 57344 B

    cudaFuncSetAttribute(k_gemm1, cudaFuncAttributeMaxDynamicSharedMemorySize, smem1);
    cudaFuncSetAttribute(k_gemm2, cudaFuncAttributeMaxDynamicSharedMemorySize, smem2);
    cudaFuncSetAttribute(k_final, cudaFuncAttributeMaxDynamicSharedMemorySize, smem3);

    k_knn<<<BB*MM/16, 256>>>(xyz, feats, out, (int*)idxp);
    k_gemm1<<<GRID_P, 256, smem1>>>(xyz, out, W1, b1);
    k_gemm2<<<GRID_P, 256, smem2>>>(W2, b2, g1, be1);
    k_final<<<GRID_P, 256, smem3>>>(Wq1, bq1, Wq2, g2, be2, out);
}

// round 16
// speedup vs baseline: 1.0601x; 1.0277x over previous
#include <cuda_runtime.h>
#include <cuda_fp16.h>
#include <math.h>
#include <float.h>

#define BB 4
#define PP 8192
#define CC 64
#define MM 2048
#define KK 32
#define CIN 67
#define H1 128
#define Q1 64
#define NPIX (BB*MM*KK)
#define BN_EPS 1e-5f
#define FULLMASK 0xffffffffu
#define NTILES 2048
#define GRID_P 296
#define XT 2048              // xyz smem tile (points per stage)

// ---------------- scratch (fp16 intermediates) ----------------
__device__ __half g_featsT[(size_t)BB*PP*CC];
__device__ int    g_idx[(size_t)BB*MM*KK];
__device__ __half g_h0[(size_t)NPIX*H1];
__device__ __half g_f0[(size_t)NPIX*H1];
__device__ float  g_stats1[2*H1];
__device__ float  g_stats2[2*H1];

// ---------------- helpers ----------------
__device__ __forceinline__ void mma16816(float* c, const unsigned* a, const unsigned* b) {
    asm volatile(
        "mma.sync.aligned.m16n8k16.row.col.f32.f16.f16.f32 "
        "{%0,%1,%2,%3}, {%4,%5,%6,%7}, {%8,%9}, {%0,%1,%2,%3};"
        : "+f"(c[0]), "+f"(c[1]), "+f"(c[2]), "+f"(c[3])
        : "r"(a[0]), "r"(a[1]), "r"(a[2]), "r"(a[3]), "r"(b[0]), "r"(b[1]));
}
__device__ __forceinline__ void cp16(unsigned dst, const void* src) {
    asm volatile("cp.async.ca.shared.global [%0], [%1], 16;\n" :: "r"(dst), "l"(src));
}
#define CP_COMMIT() asm volatile("cp.async.commit_group;\n" ::: "memory")
#define CP_WAIT(n)  asm volatile("cp.async.wait_group %0;\n" :: "n"(n) : "memory")

// ---------------- KNN: smem-tiled candidates (+ fused feats transpose, centers, stats zero) ----------------
__global__ void __launch_bounds__(256) k_knn(const float* __restrict__ xyz,
                                             const float* __restrict__ feats,
                                             float* __restrict__ out,
                                             int* __restrict__ idxout) {
    __shared__ float sxyz[XT*3];          // 24 KB
    int tid = threadIdx.x;

    {   // fused pre: transpose feats (B,C,P) -> featsT (B,P,C) fp16, 64 rows/block
        int row0 = blockIdx.x * 64;
        for (int i = tid; i < 64*32; i += 256) {
            int row = row0 + (i & 63);
            int cp  = i >> 6;
            int b = row >> 13;
            int p = row & (PP-1);
            const float* s = feats + (size_t)b*CC*PP + (size_t)(2*cp)*PP + p;
            ((__half2*)(g_featsT + (size_t)row*CC))[cp] = __floats2half2_rn(s[0], s[PP]);
        }
    }
    if (blockIdx.x == 0 && tid < 2*H1) {
        g_stats1[tid] = 0.f;
        g_stats2[tid] = 0.f;
    }

    int c0   = (blockIdx.x * 8 + (tid >> 5)) * 2;
    int lane = tid & 31;
    int b    = c0 >> 11;
    float cx[2], cy[2], cz[2], cc2[2];
#pragma unroll
    for (int jj = 0; jj < 2; jj++) {
        int ci = c0 + jj;
        int m  = ci & (MM-1);
        int pc;
        if (m == MM-1) pc = PP-1;
        else {
            float t = __fdiv_rn((float)m, (float)(MM-1));
            float v = __fmul_rn((float)(PP-1), t);
            pc = (int)v;
            if (pc > PP-1) pc = PP-1;
        }
        const float* s = xyz + ((size_t)(b*PP + pc))*3;
        cx[jj] = s[0]; cy[jj] = s[1]; cz[jj] = s[2];
        cc2[jj] = cx[jj]*cx[jj] + cy[jj]*cy[jj] + cz[jj]*cz[jj];
        if (lane == jj) {
            out[(size_t)ci*3 + 0] = cx[jj];
            out[(size_t)ci*3 + 1] = cy[jj];
            out[(size_t)ci*3 + 2] = cz[jj];
        }
    }
    const float* xb = xyz + (size_t)b*PP*3;

    float ld[2] = {FLT_MAX, FLT_MAX};
    int   li[2] = {0x7fffffff, 0x7fffffff};
    float kth[2] = {FLT_MAX, FLT_MAX};

    for (int stage = 0; stage < PP/XT; stage++) {
        __syncthreads();
        {   // stage XT points (24KB) into smem, float4 coalesced
            const float4* src = (const float4*)(xb + (size_t)stage*XT*3);
            for (int i = tid; i < XT*3/4; i += 256)
                ((float4*)sxyz)[i] = src[i];
        }
        __syncthreads();
        for (int ii = 0; ii < XT/32; ii++) {
            int pl = ii*32 + lane;
            float x = sxyz[3*pl], y = sxyz[3*pl+1], z = sxyz[3*pl+2];
            float x2 = x*x + y*y + z*z;
            int base = stage*XT + ii*32;
#pragma unroll
            for (int jj = 0; jj < 2; jj++) {
                float d = (cc2[jj] + x2) - 2.0f*(cx[jj]*x + cy[jj]*y + cz[jj]*z);
                unsigned mask = __ballot_sync(FULLMASK, d < kth[jj]);
                while (mask) {
                    int j = __ffs(mask) - 1; mask &= mask - 1;
                    float dj = __shfl_sync(FULLMASK, d, j);
                    if (dj < kth[jj]) {
                        int pj = base + j;
                        unsigned lt = __ballot_sync(FULLMASK,
                            (ld[jj] < dj) || (ld[jj] == dj && li[jj] < pj));
                        int pos = __popc(lt);
                        float pd = __shfl_up_sync(FULLMASK, ld[jj], 1);
                        int   pi = __shfl_up_sync(FULLMASK, li[jj], 1);
                        if (lane == pos)      { ld[jj] = dj; li[jj] = pj; }
                        else if (lane > pos)  { ld[jj] = pd; li[jj] = pi; }
                        kth[jj] = __shfl_sync(FULLMASK, ld[jj], 31);
                    }
                }
            }
        }
    }
#pragma unroll
    for (int jj = 0; jj < 2; jj++)
        idxout[(size_t)(c0 + jj)*KK + lane] = li[jj];
}

// ================= GEMM1: persistent tiles, cp.async double-buffered gather + MMA =================
__global__ void __launch_bounds__(256, 2) k_gemm1(const float* __restrict__ xyz,
                                                  const float* __restrict__ centers,
                                                  const float* __restrict__ W1,
                                                  const float* __restrict__ b1) {
    extern __shared__ __half sh[];
    __half* Ab = sh;                       // 2 * 128*88
    __half* Bs = sh + 2*128*88;
    unsigned* Bw = (unsigned*)Bs;

    int tid = threadIdx.x, wid = tid >> 5, lane = tid & 31;
    int g = lane >> 2, t = lane & 3;
    int warp_pix = (wid >> 2) * 64, warp_n = (wid & 3) * 32;
    int r = tid >> 1, h = tid & 1;

    for (int i = tid; i < 128*44; i += 256) Bw[i] = 0u;
    {
        __half z = __float2half_rn(0.f);
#pragma unroll
        for (int bufi = 0; bufi < 2; bufi++)
            if (h == 1)
                for (int q = 64; q < 88; q++) Ab[bufi*128*88 + r*88 + q] = z;
    }
    __syncthreads();
    for (int i = tid; i < H1*CIN; i += 256) {
        int o = i / CIN, c = i - o*CIN;
        int col = (c < 3) ? (64 + c) : (c - 3);
        Bs[o*88 + col] = __float2half_rn(W1[i]);
    }
    float bias0[4], bias1[4];
#pragma unroll
    for (int ni = 0; ni < 4; ni++) {
        bias0[ni] = b1[warp_n + ni*8 + 2*t];
        bias1[ni] = b1[warp_n + ni*8 + 2*t + 1];
    }
    unsigned abase = (unsigned)__cvta_generic_to_shared(Ab);

    float ss[4][2], sq[4][2];
#pragma unroll
    for (int ni = 0; ni < 4; ni++) { ss[ni][0]=ss[ni][1]=0.f; sq[ni][0]=sq[ni][1]=0.f; }

    auto stage = [&](int tt, int bufi) {
        int b = tt >> 9, m0 = (tt & 511) << 2;
        size_t pixbase = ((size_t)(b*MM + m0))*KK;
        int p = g_idx[pixbase + r];
        const char* srcp = (const char*)(g_featsT + ((size_t)(b*PP + p))*CC) + h*64;
        unsigned sdst = abase + (unsigned)(bufi*128*88 + r*88)*2 + h*64;
#pragma unroll
        for (int q = 0; q < 4; q++) cp16(sdst + q*16, srcp + q*16);
        if (h == 0) {
            int m = m0 + (r >> 5);
            const float* xp = xyz + ((size_t)(b*PP + p))*3;
            const float* cpt = centers + ((size_t)(b*MM + m))*3;
            __half2* A2 = (__half2*)(Ab + bufi*128*88);
            A2[r*44 + 32] = __floats2half2_rn(xp[0]-cpt[0], xp[1]-cpt[1]);
            A2[r*44 + 33] = __floats2half2_rn(xp[2]-cpt[2], 0.f);
        }
        CP_COMMIT();
    };

    int tt = blockIdx.x;
    int bufi = 0;
    stage(tt, 0);
    while (tt < NTILES) {
        int nxt = tt + GRID_P;
        if (nxt < NTILES) { stage(nxt, bufi^1); CP_WAIT(1); }
        else CP_WAIT(0);
        __syncthreads();

        const unsigned* Aw = (const unsigned*)(Ab + bufi*128*88);
        int b = tt >> 9, m0 = (tt & 511) << 2;
        size_t pixbase = ((size_t)(b*MM + m0))*KK;

        float acc[4][4][4];
#pragma unroll
        for (int mi = 0; mi < 4; mi++)
#pragma unroll
            for (int ni = 0; ni < 4; ni++) {
                acc[mi][ni][0] = bias0[ni]; acc[mi][ni][1] = bias1[ni];
                acc[mi][ni][2] = bias0[ni]; acc[mi][ni][3] = bias1[ni];
            }
#pragma unroll
        for (int ks = 0; ks < 5; ks++) {
            int kw = ks*8;
            unsigned af[4][4], bf[4][2];
#pragma unroll
            for (int mi = 0; mi < 4; mi++) {
                int rr = warp_pix + mi*16 + g;
                af[mi][0] = Aw[rr*44 + t + kw];
                af[mi][1] = Aw[(rr+8)*44 + t + kw];
                af[mi][2] = Aw[rr*44 + t + 4 + kw];
                af[mi][3] = Aw[(rr+8)*44 + t + 4 + kw];
            }
#pragma unroll
            for (int ni = 0; ni < 4; ni++) {
                int nn = warp_n + ni*8 + g;
                bf[ni][0] = Bw[nn*44 + t + kw];
                bf[ni][1] = Bw[nn*44 + t + 4 + kw];
            }
#pragma unroll
            for (int mi = 0; mi < 4; mi++)
#pragma unroll
                for (int ni = 0; ni < 4; ni++)
                    mma16816(acc[mi][ni], af[mi], bf[ni]);
        }
#pragma unroll
        for (int mi = 0; mi < 4; mi++) {
            int row = warp_pix + mi*16 + g;
#pragma unroll
            for (int ni = 0; ni < 4; ni++) {
                int col = warp_n + ni*8 + 2*t;
                float* a = acc[mi][ni];
                *(__half2*)&g_h0[(pixbase + row)*H1 + col]     = __floats2half2_rn(a[0], a[1]);
                *(__half2*)&g_h0[(pixbase + row + 8)*H1 + col] = __floats2half2_rn(a[2], a[3]);
                ss[ni][0] += a[0] + a[2];  ss[ni][1] += a[1] + a[3];
                sq[ni][0] = fmaf(a[0], a[0], sq[ni][0]);
                sq[ni][0] = fmaf(a[2], a[2], sq[ni][0]);
                sq[ni][1] = fmaf(a[1], a[1], sq[ni][1]);
                sq[ni][1] = fmaf(a[3], a[3], sq[ni][1]);
            }
        }
        __syncthreads();
        bufi ^= 1; tt = nxt;
    }
#pragma unroll
    for (int ni = 0; ni < 4; ni++)
#pragma unroll
        for (int j = 0; j < 2; j++) {
            float s = ss[ni][j], q = sq[ni][j];
            s += __shfl_xor_sync(FULLMASK, s, 4);  q += __shfl_xor_sync(FULLMASK, q, 4);
            s += __shfl_xor_sync(FULLMASK, s, 8);  q += __shfl_xor_sync(FULLMASK, q, 8);
            s += __shfl_xor_sync(FULLMASK, s, 16); q += __shfl_xor_sync(FULLMASK, q, 16);
            if (g == 0) {
                int o = warp_n + ni*8 + 2*t + j;
                atomicAdd(&g_stats1[o], s);
                atomicAdd(&g_stats1[H1 + o], q);
            }
        }
}

// ================= GEMM2: persistent tiles, fused BN1-affine =================
__global__ void __launch_bounds__(256, 2) k_gemm2(const float* __restrict__ W2,
                                                  const float* __restrict__ b2,
                                                  const float* __restrict__ g1,
                                                  const float* __restrict__ be1) {
    extern __shared__ __half sh[];
    __half* As = sh;                  // 128*136
    __half* Bs = sh + 128*136;
    float* aff1s = (float*)(sh + 2*128*136);
    unsigned* Aw = (unsigned*)As;
    unsigned* Bw = (unsigned*)Bs;
    __half2* Ah2 = (__half2*)As;
    __half2* Bh2 = (__half2*)Bs;

    int tid = threadIdx.x, wid = tid >> 5, lane = tid & 31;
    int g = lane >> 2, t = lane & 3;
    int warp_pix = (wid >> 2) * 64, warp_n = (wid & 3) * 32;
    int r = tid >> 1, h = tid & 1;

    for (int i = tid; i < H1*64; i += 256) {
        int o = i >> 6, wp = i & 63;
        float2 v = ((const float2*)W2)[o*64 + wp];
        Bh2[o*68 + wp] = __floats2half2_rn(v.x, v.y);
    }
    if (tid < H1) {
        float inv = 1.0f / (float)NPIX;
        float mean = g_stats1[tid] * inv;
        float var  = g_stats1[H1 + tid] * inv - mean*mean;
        float a = g1[tid] * rsqrtf(var + BN_EPS);
        aff1s[tid] = a;
        aff1s[H1 + tid] = be1[tid] - a*mean;
    }
    float bias0[4], bias1[4];
#pragma unroll
    for (int ni = 0; ni < 4; ni++) {
        bias0[ni] = b2[warp_n + ni*8 + 2*t];
        bias1[ni] = b2[warp_n + ni*8 + 2*t + 1];
    }

    float ss[4][2], sq[4][2];
#pragma unroll
    for (int ni = 0; ni < 4; ni++) { ss[ni][0]=ss[ni][1]=0.f; sq[ni][0]=sq[ni][1]=0.f; }

    for (int tt = blockIdx.x; tt < NTILES; tt += GRID_P) {
        int b = tt >> 9, m0 = (tt & 511) << 2;
        size_t pixbase = ((size_t)(b*MM + m0))*KK;
        __syncthreads();
        {   // load fp16 h0, bn1+relu fp32, repack fp16
            const uint4* src = (const uint4*)(g_h0 + (pixbase + r)*H1) + h*8;
            int wbase = r*68 + h*32;
#pragma unroll
            for (int q = 0; q < 8; q++) {
                uint4 v = src[q];
                int c = h*64 + q*8;
                const __half2* hv = (const __half2*)&v;
#pragma unroll
                for (int i2 = 0; i2 < 4; i2++) {
                    float2 f = __half22float2(hv[i2]);
                    float2 a = *(const float2*)&aff1s[c + 2*i2];
                    float2 cc = *(const float2*)&aff1s[H1 + c + 2*i2];
                    f.x = fmaxf(fmaf(a.x, f.x, cc.x), 0.f);
                    f.y = fmaxf(fmaf(a.y, f.y, cc.y), 0.f);
                    Ah2[wbase + q*4 + i2] = __floats2half2_rn(f.x, f.y);
                }
            }
        }
        __syncthreads();

        float acc[4][4][4];
#pragma unroll
        for (int mi = 0; mi < 4; mi++)
#pragma unroll
            for (int ni = 0; ni < 4; ni++) {
                acc[mi][ni][0] = bias0[ni]; acc[mi][ni][1] = bias1[ni];
                acc[mi][ni][2] = bias0[ni]; acc[mi][ni][3] = bias1[ni];
            }
#pragma unroll
        for (int ks = 0; ks < 8; ks++) {
            int kw = ks*8;
            unsigned af[4][4], bf[4][2];
#pragma unroll
            for (int mi = 0; mi < 4; mi++) {
                int rr = warp_pix + mi*16 + g;
                af[mi][0] = Aw[rr*68 + t + kw];
                af[mi][1] = Aw[(rr+8)*68 + t + kw];
                af[mi][2] = Aw[rr*68 + t + 4 + kw];
                af[mi][3] = Aw[(rr+8)*68 + t + 4 + kw];
            }
#pragma unroll
            for (int ni = 0; ni < 4; ni++) {
                int nn = warp_n + ni*8 + g;
                bf[ni][0] = Bw[nn*68 + t + kw];
                bf[ni][1] = Bw[nn*68 + t + 4 + kw];
            }
#pragma unroll
            for (int mi = 0; mi < 4; mi++)
#pragma unroll
                for (int ni = 0; ni < 4; ni++)
                    mma16816(acc[mi][ni], af[mi], bf[ni]);
        }
#pragma unroll
        for (int mi = 0; mi < 4; mi++) {
            int row = warp_pix + mi*16 + g;
#pragma unroll
            for (int ni = 0; ni < 4; ni++) {
                int col = warp_n + ni*8 + 2*t;
                float* a = acc[mi][ni];
                *(__half2*)&g_f0[(pixbase + row)*H1 + col]     = __floats2half2_rn(a[0], a[1]);
                *(__half2*)&g_f0[(pixbase + row + 8)*H1 + col] = __floats2half2_rn(a[2], a[3]);
                ss[ni][0] += a[0] + a[2];  ss[ni][1] += a[1] + a[3];
                sq[ni][0] = fmaf(a[0], a[0], sq[ni][0]);
                sq[ni][0] = fmaf(a[2], a[2], sq[ni][0]);
                sq[ni][1] = fmaf(a[1], a[1], sq[ni][1]);
                sq[ni][1] = fmaf(a[3], a[3], sq[ni][1]);
            }
        }
    }
#pragma unroll
    for (int ni = 0; ni < 4; ni++)
#pragma unroll
        for (int j = 0; j < 2; j++) {
            float s = ss[ni][j], q = sq[ni][j];
            s += __shfl_xor_sync(FULLMASK, s, 4);  q += __shfl_xor_sync(FULLMASK, q, 4);
            s += __shfl_xor_sync(FULLMASK, s, 8);  q += __shfl_xor_sync(FULLMASK, q, 8);
            s += __shfl_xor_sync(FULLMASK, s, 16); q += __shfl_xor_sync(FULLMASK, q, 16);
            if (g == 0) {
                int o = warp_n + ni*8 + 2*t + j;
                atomicAdd(&g_stats2[o], s);
                atomicAdd(&g_stats2[H1 + o], q);
            }
        }
}

// ================= final: persistent tiles, fused BN2-affine, q-GEMM, softmax, coalesced out ====
__global__ void __launch_bounds__(256, 2) k_final(const float* __restrict__ Wq1,
                                                  const float* __restrict__ bq1,
                                                  const float* __restrict__ Wq2,
                                                  const float* __restrict__ g2,
                                                  const float* __restrict__ be2,
                                                  float* __restrict__ out) {
    extern __shared__ __half sh[];
    __half* As = sh;                  // 128*136
    __half* Bs = sh + 128*136;        // 64*136
    float* aff2s = (float*)(sh + 128*136 + 64*136);
    float* bq1s  = aff2s + 2*H1;
    float* wq2s  = bq1s + Q1;
    float* slog0 = wq2s + Q1;
    float* slog1 = slog0 + 128;
    float* wk    = slog1 + 128;
    float* outb  = wk + 128;          // 512 floats: [mm][o]
    unsigned* Aw = (unsigned*)As;
    unsigned* Bw = (unsigned*)Bs;
    __half2* Ah2 = (__half2*)As;
    __half2* Bh2 = (__half2*)Bs;

    int tid = threadIdx.x, wid = tid >> 5, lane = tid & 31;
    int g = lane >> 2, t = lane & 3;
    int warp_pix = (wid & 3) * 32, warp_n = (wid >> 2) * 32;
    int r = tid >> 1, h = tid & 1;

    for (int i = tid; i < Q1*64; i += 256) {
        int n = i >> 6, wp = i & 63;
        float2 v = ((const float2*)Wq1)[n*64 + wp];
        Bh2[n*68 + wp] = __floats2half2_rn(v.x, v.y);
    }
    if (tid < H1) {
        float inv = 1.0f / (float)NPIX;
        float mean = g_stats2[tid] * inv;
        float var  = g_stats2[H1 + tid] * inv - mean*mean;
        float a = g2[tid] * rsqrtf(var + BN_EPS);
        aff2s[tid] = a;
        aff2s[H1 + tid] = be2[tid] - a*mean;
    }
    if (tid < Q1) { bq1s[tid] = bq1[tid]; wq2s[tid] = Wq2[tid]; }

    float bias0[4], bias1[4], w20[4], w21[4];
    __syncthreads();
#pragma unroll
    for (int ni = 0; ni < 4; ni++) {
        bias0[ni] = bq1s[warp_n + ni*8 + 2*t];
        bias1[ni] = bq1s[warp_n + ni*8 + 2*t + 1];
        w20[ni]   = wq2s[warp_n + ni*8 + 2*t];
        w21[ni]   = wq2s[warp_n + ni*8 + 2*t + 1];
    }

    for (int tt = blockIdx.x; tt < NTILES; tt += GRID_P) {
        int b = tt >> 9, m0 = (tt & 511) << 2;
        size_t pixbase = ((size_t)(b*MM + m0))*KK;
        size_t obase = (size_t)BB*MM*3 + (size_t)b*H1*MM;
        __syncthreads();
        {   // load fp16 f0, bn2+relu fp32 math, repack fp16
            const uint4* src = (const uint4*)(g_f0 + (pixbase + r)*H1) + h*8;
            int wbase = r*68 + h*32;
#pragma unroll
            for (int q = 0; q < 8; q++) {
                uint4 v = src[q];
                int c = h*64 + q*8;
                const __half2* hv = (const __half2*)&v;
#pragma unroll
                for (int i2 = 0; i2 < 4; i2++) {
                    float2 f = __half22float2(hv[i2]);
                    float2 a = *(const float2*)&aff2s[c + 2*i2];
                    float2 cc = *(const float2*)&aff2s[H1 + c + 2*i2];
                    f.x = fmaxf(fmaf(a.x, f.x, cc.x), 0.f);
                    f.y = fmaxf(fmaf(a.y, f.y, cc.y), 0.f);
                    Ah2[wbase + q*4 + i2] = __floats2half2_rn(f.x, f.y);
                }
            }
        }
        __syncthreads();

        float acc[2][4][4];
#pragma unroll
        for (int mi = 0; mi < 2; mi++)
#pragma unroll
            for (int ni = 0; ni < 4; ni++) {
                acc[mi][ni][0] = bias0[ni]; acc[mi][ni][1] = bias1[ni];
                acc[mi][ni][2] = bias0[ni]; acc[mi][ni][3] = bias1[ni];
            }
#pragma unroll
        for (int ks = 0; ks < 8; ks++) {
            int kw = ks*8;
            unsigned af[2][4], bf[4][2];
#pragma unroll
            for (int mi = 0; mi < 2; mi++) {
                int rr = warp_pix + mi*16 + g;
                af[mi][0] = Aw[rr*68 + t + kw];
                af[mi][1] = Aw[(rr+8)*68 + t + kw];
                af[mi][2] = Aw[rr*68 + t + 4 + kw];
                af[mi][3] = Aw[(rr+8)*68 + t + 4 + kw];
            }
#pragma unroll
            for (int ni = 0; ni < 4; ni++) {
                int nn = warp_n + ni*8 + g;
                bf[ni][0] = Bw[nn*68 + t + kw];
                bf[ni][1] = Bw[nn*68 + t + 4 + kw];
            }
#pragma unroll
            for (int mi = 0; mi < 2; mi++)
#pragma unroll
                for (int ni = 0; ni < 4; ni++)
                    mma16816(acc[mi][ni], af[mi], bf[ni]);
        }

        // logits partial: s(pix) = sum_j wq2[j] * relu(q_j)
        float* sl = (wid < 4) ? slog0 : slog1;
#pragma unroll
        for (int mi = 0; mi < 2; mi++) {
            float p0 = 0.f, p1 = 0.f;
#pragma unroll
            for (int ni = 0; ni < 4; ni++) {
                float* a = acc[mi][ni];
                p0 = fmaf(w20[ni], fmaxf(a[0], 0.f), p0);
                p0 = fmaf(w21[ni], fmaxf(a[1], 0.f), p0);
                p1 = fmaf(w20[ni], fmaxf(a[2], 0.f), p1);
                p1 = fmaf(w21[ni], fmaxf(a[3], 0.f), p1);
            }
            p0 += __shfl_xor_sync(FULLMASK, p0, 1);
            p0 += __shfl_xor_sync(FULLMASK, p0, 2);
            p1 += __shfl_xor_sync(FULLMASK, p1, 1);
            p1 += __shfl_xor_sync(FULLMASK, p1, 2);
            if (t == 0) {
                sl[warp_pix + mi*16 + g]     = p0;
                sl[warp_pix + mi*16 + 8 + g] = p1;
            }
        }
        __syncthreads();
        if (wid < 4) {   // softmax per m over 32 neighbors (bq2 shift-invariant)
            int idx = wid*32 + lane;
            float s = slog0[idx] + slog1[idx];
            float mx = s;
#pragma unroll
            for (int off = 16; off; off >>= 1)
                mx = fmaxf(mx, __shfl_xor_sync(FULLMASK, mx, off));
            float e = expf(s - mx);
            float sum = e;
#pragma unroll
            for (int off = 16; off; off >>= 1)
                sum += __shfl_xor_sync(FULLMASK, sum, off);
            wk[idx] = e / sum;
        }
        __syncthreads();
        {   // aggregate via half2 reads, then coalesced out
            int o2 = tid & 63, mm = tid >> 6;
            float a0 = 0.f, a1 = 0.f;
#pragma unroll
            for (int kn = 0; kn < 32; kn++) {
                float2 f = __half22float2(Ah2[(mm*32 + kn)*68 + o2]);
                float w = wk[mm*32 + kn];
                a0 = fmaf(f.x, w, a0);
                a1 = fmaf(f.y, w, a1);
            }
            outb[mm*128 + 2*o2]     = a0;
            outb[mm*128 + 2*o2 + 1] = a1;
        }
        __syncthreads();
        if (tid < 128) {
            float4 v;
            v.x = outb[0*128 + tid];
            v.y = outb[1*128 + tid];
            v.z = outb[2*128 + tid];
            v.w = outb[3*128 + tid];
            *(float4*)&out[obase + (size_t)tid*MM + m0] = v;
        }
    }
}

// ---------------- launch ----------------
extern "C" void kernel_launch(void* const* d_in, const int* in_sizes, int n_in,
                              void* d_out, int out_size) {
    const float* xyz  = (const float*)d_in[0];
    const float* feats= (const float*)d_in[1];
    const float* W1   = (const float*)d_in[2];
    const float* b1   = (const float*)d_in[3];
    const float* g1   = (const float*)d_in[4];
    const float* be1  = (const float*)d_in[5];
    const float* W2   = (const float*)d_in[6];
    const float* b2   = (const float*)d_in[7];
    const float* g2   = (const float*)d_in[8];
    const float* be2  = (const float*)d_in[9];
    const float* Wq1  = (const float*)d_in[10];
    const float* bq1  = (const float*)d_in[11];
    const float* Wq2  = (const float*)d_in[12];
    float* out = (float*)d_out;

    void *idxp;
    cudaGetSymbolAddress(&idxp, g_idx);

    const int smem1 = (2*128*88 + 128*88)*2;                                // 67584 B
    const int smem2 = 2*128*136*2 + 2*H1*4;                                 // 70656 B
    const int smem3 = (128*136 + 64*136)*2 + (2*H1 + 2*Q1 + 3*128 + 512)*4; // 57344 B

    cudaFuncSetAttribute(k_gemm1, cudaFuncAttributeMaxDynamicSharedMemorySize, smem1);
    cudaFuncSetAttribute(k_gemm2, cudaFuncAttributeMaxDynamicSharedMemorySize, smem2);
    cudaFuncSetAttribute(k_final, cudaFuncAttributeMaxDynamicSharedMemorySize, smem3);

    k_knn<<<BB*MM/16, 256>>>(xyz, feats, out, (int*)idxp);
    k_gemm1<<<GRID_P, 256, smem1>>>(xyz, out, W1, b1);
    k_gemm2<<<GRID_P, 256, smem2>>>(W2, b2, g1, be1);
    k_final<<<GRID_P, 256, smem3>>>(Wq1, bq1, Wq2, g2, be2, out);
}